// round 6
// baseline (speedup 1.0000x reference)
#include <cuda_runtime.h>
#include <cstdint>

// Masked mean over first xs_len[b] rows of xs[b]: out[b][d] = sum_{s<L} xs[b][s][d] / L
// xs: [16, 4096, 512] f32, xs_len: [16] (int32 OR int64 -- decoded at runtime), out: [16, 512] f32
// Single fused kernel: per-split partial sums + "last block per batch" reduction.

#define B 16
#define S 4096
#define D 512
#define D4 (D / 4)                   // 128 float4 per row
#define SPLIT 64
#define ROWS_PER_SPLIT (S / SPLIT)   // 64

// Scratch partials: [B][SPLIT][D4] float4 = 2 MiB. Only splits with s0 < L are
// ever written AND read in a given launch -> deterministic.
__device__ float4 g_partial[B * SPLIT * D4];
// Per-batch arrival counters. Statically zero-initialized; the last block of
// each batch resets its counter to 0 before exiting -> graph-replay safe.
__device__ int g_count[B];

// Robust length decode: if the buffer is int64, value is in [1, S].
// If it is int32, the 64-bit read packs two lengths (both >= 1) and falls
// outside [1, S] -> fall back to the int32 read.
__device__ __forceinline__ int decode_len(const void* xs_len, int b) {
    long long v64 = ((const long long*)xs_len)[b];
    if (v64 >= 1 && v64 <= (long long)S) return (int)v64;
    return ((const int*)xs_len)[b];
}

__global__ void __launch_bounds__(D4, 8)
mean_fused_kernel(const float* __restrict__ xs,
                  const void* __restrict__ xs_len,
                  float* __restrict__ out) {
    const int sp = blockIdx.x;          // split index  [0, SPLIT)
    const int b  = blockIdx.y;          // batch index  [0, B)
    const int t  = threadIdx.x;         // float4 column [0, D4)

    const int L = decode_len(xs_len, b);
    const int n_valid = (L + ROWS_PER_SPLIT - 1) / ROWS_PER_SPLIT;  // splits with data

    const int s0 = sp * ROWS_PER_SPLIT;
    if (s0 < L) {
        int s1 = s0 + ROWS_PER_SPLIT;
        if (s1 > L) s1 = L;

        const float4* __restrict__ base =
            reinterpret_cast<const float4*>(xs + (size_t)b * S * D) + t;

        float4 acc = make_float4(0.f, 0.f, 0.f, 0.f);

        int s = s0;
        // Unrolled by 8: 8 independent 16B loads in flight per thread (MLP=8)
        for (; s + 8 <= s1; s += 8) {
            float4 v0 = base[(size_t)(s + 0) * D4];
            float4 v1 = base[(size_t)(s + 1) * D4];
            float4 v2 = base[(size_t)(s + 2) * D4];
            float4 v3 = base[(size_t)(s + 3) * D4];
            float4 v4 = base[(size_t)(s + 4) * D4];
            float4 v5 = base[(size_t)(s + 5) * D4];
            float4 v6 = base[(size_t)(s + 6) * D4];
            float4 v7 = base[(size_t)(s + 7) * D4];
            acc.x += (v0.x + v1.x) + (v2.x + v3.x) + (v4.x + v5.x) + (v6.x + v7.x);
            acc.y += (v0.y + v1.y) + (v2.y + v3.y) + (v4.y + v5.y) + (v6.y + v7.y);
            acc.z += (v0.z + v1.z) + (v2.z + v3.z) + (v4.z + v5.z) + (v6.z + v7.z);
            acc.w += (v0.w + v1.w) + (v2.w + v3.w) + (v4.w + v5.w) + (v6.w + v7.w);
        }
        for (; s < s1; s++) {
            float4 v = base[(size_t)s * D4];
            acc.x += v.x; acc.y += v.y; acc.z += v.z; acc.w += v.w;
        }

        g_partial[(b * SPLIT + sp) * D4 + t] = acc;
    }

    // Arrival protocol: make this block's partial globally visible, then count.
    __threadfence();
    __shared__ int is_last;
    __syncthreads();               // all threads' STG issued before the fence/arrival
    if (t == 0) {
        int prev = atomicAdd(&g_count[b], 1);
        is_last = (prev == SPLIT - 1);
    }
    __syncthreads();

    if (is_last) {
        // This block is the last arrival for batch b: all valid partials are
        // visible (fence + atomic ordering). Fixed-order summation -> deterministic.
        const float4* __restrict__ pbase = &g_partial[(size_t)b * SPLIT * D4 + t];

        float4 r = make_float4(0.f, 0.f, 0.f, 0.f);
        int k = 0;
#pragma unroll 4
        for (; k + 4 <= n_valid; k += 4) {
            float4 v0 = pbase[(size_t)(k + 0) * D4];
            float4 v1 = pbase[(size_t)(k + 1) * D4];
            float4 v2 = pbase[(size_t)(k + 2) * D4];
            float4 v3 = pbase[(size_t)(k + 3) * D4];
            r.x += (v0.x + v1.x) + (v2.x + v3.x);
            r.y += (v0.y + v1.y) + (v2.y + v3.y);
            r.z += (v0.z + v1.z) + (v2.z + v3.z);
            r.w += (v0.w + v1.w) + (v2.w + v3.w);
        }
        for (; k < n_valid; k++) {
            float4 v = pbase[(size_t)k * D4];
            r.x += v.x; r.y += v.y; r.z += v.z; r.w += v.w;
        }

        const float inv = 1.0f / (float)L;
        r.x *= inv; r.y *= inv; r.z *= inv; r.w *= inv;
        reinterpret_cast<float4*>(out)[b * D4 + t] = r;

        if (t == 0) g_count[b] = 0;   // reset for next graph replay
    }
}

extern "C" void kernel_launch(void* const* d_in, const int* in_sizes, int n_in,
                              void* d_out, int out_size) {
    const float* xs = (const float*)d_in[0];
    const void* xs_len = d_in[1];
    float* out = (float*)d_out;

    dim3 grid(SPLIT, B);
    mean_fused_kernel<<<grid, D4>>>(xs, xs_len, out);
}

// round 8
// speedup vs baseline: 1.1910x; 1.1910x over previous
#include <cuda_runtime.h>
#include <cstdint>

// Masked mean over first xs_len[b] rows of xs[b]: out[b][d] = sum_{s<L} xs[b][s][d] / L
// xs: [16, 4096, 512] f32, xs_len: [16] (int32 OR int64 -- decoded at runtime), out: [16, 512] f32

#define B 16
#define S 4096
#define D 512
#define D4 (D / 4)                   // 128 float4 per row
#define SPLIT 64
#define ROWS_PER_SPLIT (S / SPLIT)   // 64

// Deterministic scratch for partial sums: [B][SPLIT][D4] float4 = 2 MiB.
// Fully written by every K1 launch (zero partials included), so no init needed.
__device__ float4 g_partial[B * SPLIT * D4];

// Robust length decode: int64 value lies in [1, S]; an int32 buffer read as
// int64 packs two lengths (both >= 1) and falls outside [1, S].
__device__ __forceinline__ int decode_len(const void* xs_len, int b) {
    long long v64 = ((const long long*)xs_len)[b];
    if (v64 >= 1 && v64 <= (long long)S) return (int)v64;
    return ((const int*)xs_len)[b];
}

// K1: grid (SPLIT, B), 256 threads. Threads arranged as (half, col):
//   col  = t & 127  -> float4 column
//   half = t >> 7   -> rows s0+half, s0+half+2, ... (stride 2)
// Each half accumulates 32 rows (unroll 8 -> 8 LDG.128 in flight / thread),
// then a 2-way shared-memory fold produces the split partial.
__global__ void __launch_bounds__(256, 6)
mean_partial_kernel(const float* __restrict__ xs,
                    const void* __restrict__ xs_len) {
    const int sp   = blockIdx.x;
    const int b    = blockIdx.y;
    const int t    = threadIdx.x;
    const int col  = t & (D4 - 1);
    const int half = t >> 7;

    const int L = decode_len(xs_len, b);
    const int s0 = sp * ROWS_PER_SPLIT;
    int s1 = s0 + ROWS_PER_SPLIT;
    if (s1 > L) s1 = L;

    const float4* __restrict__ base =
        reinterpret_cast<const float4*>(xs + (size_t)b * S * D) + col;

    float4 acc = make_float4(0.f, 0.f, 0.f, 0.f);

    int s = s0 + half;
    // 8 independent loads in flight (rows s, s+2, ..., s+14)
    for (; s + 14 < s1; s += 16) {
        float4 v0 = base[(size_t)(s +  0) * D4];
        float4 v1 = base[(size_t)(s +  2) * D4];
        float4 v2 = base[(size_t)(s +  4) * D4];
        float4 v3 = base[(size_t)(s +  6) * D4];
        float4 v4 = base[(size_t)(s +  8) * D4];
        float4 v5 = base[(size_t)(s + 10) * D4];
        float4 v6 = base[(size_t)(s + 12) * D4];
        float4 v7 = base[(size_t)(s + 14) * D4];
        acc.x += (v0.x + v1.x) + (v2.x + v3.x) + (v4.x + v5.x) + (v6.x + v7.x);
        acc.y += (v0.y + v1.y) + (v2.y + v3.y) + (v4.y + v5.y) + (v6.y + v7.y);
        acc.z += (v0.z + v1.z) + (v2.z + v3.z) + (v4.z + v5.z) + (v6.z + v7.z);
        acc.w += (v0.w + v1.w) + (v2.w + v3.w) + (v4.w + v5.w) + (v6.w + v7.w);
    }
    for (; s < s1; s += 2) {
        float4 v = base[(size_t)s * D4];
        acc.x += v.x; acc.y += v.y; acc.z += v.z; acc.w += v.w;
    }

    __shared__ float4 sm[256];
    sm[t] = acc;
    __syncthreads();

    if (half == 0) {
        float4 o = sm[t + 128];
        acc.x += o.x; acc.y += o.y; acc.z += o.z; acc.w += o.w;
        g_partial[(b * SPLIT + sp) * D4 + col] = acc;
    }
}

// K2: grid B*16 CTAs, 128 threads. CTA (b, g) covers float4 cols [g*8, g*8+8).
//   t = sp_grp*8 + c : sp_grp in [0,16) sums 4 splits; c in [0,8) is the column.
// 16-way fold done as 4-deep tree in shared memory (fixed order -> deterministic).
__global__ void __launch_bounds__(128)
mean_finalize_kernel(const void* __restrict__ xs_len,
                     float* __restrict__ out) {
    const int b = blockIdx.x >> 4;      // batch
    const int g = blockIdx.x & 15;      // column group: float4 cols [g*8, g*8+8)
    const int t = threadIdx.x;
    const int sp_grp = t >> 3;          // [0,16): which 4-split chunk
    const int c      = t & 7;           // [0,8): float4 column within group

    const int col4 = g * 8 + c;
    const float4* __restrict__ base = &g_partial[(size_t)b * SPLIT * D4 + col4];

    float4 acc = make_float4(0.f, 0.f, 0.f, 0.f);
#pragma unroll
    for (int k = 0; k < 4; k++) {
        float4 v = base[(size_t)(sp_grp * 4 + k) * D4];
        acc.x += v.x; acc.y += v.y; acc.z += v.z; acc.w += v.w;
    }

    __shared__ float4 sm[128];
    sm[t] = acc;
    __syncthreads();

    if (t < 8) {
        float4 r = sm[t];
#pragma unroll
        for (int k = 1; k < 16; k++) {
            float4 v = sm[t + 8 * k];
            r.x += v.x; r.y += v.y; r.z += v.z; r.w += v.w;
        }
        const float inv = 1.0f / (float)decode_len(xs_len, b);
        r.x *= inv; r.y *= inv; r.z *= inv; r.w *= inv;
        reinterpret_cast<float4*>(out)[b * D4 + g * 8 + t] = r;
    }
}

extern "C" void kernel_launch(void* const* d_in, const int* in_sizes, int n_in,
                              void* d_out, int out_size) {
    const float* xs = (const float*)d_in[0];
    const void* xs_len = d_in[1];
    float* out = (float*)d_out;

    dim3 grid1(SPLIT, B);
    mean_partial_kernel<<<grid1, 256>>>(xs, xs_len);
    mean_finalize_kernel<<<B * 16, 128>>>(xs_len, out);
}